// round 7
// baseline (speedup 1.0000x reference)
#include <cuda_runtime.h>
#include <cuda_fp16.h>
#include <stdint.h>

#define GD 10000
#define GN 10001
#define GH 1024
#define GM 4096
#define NPAD 10112

#define MT 128
#define NT 128
#define KT 64
#define NSTAGE 16           // K = 1024, fp16-hi term only
#define TPB 256
#define STG_BYTES 32768u
#define SMEM_ALLOC (3u * STG_BYTES)

#define SEL_EPS 1e-10f
#define CAND_SLACK 45.0f
#define WCAP 64             // per-warp candidate capacity

// fp16 hi planes (device scratch, .bss)
__device__ __half g_Ah[GM * GH];
__device__ __half g_Bh[NPAD * GH];

// ============================ helpers ============================
__device__ __forceinline__ uint32_t smem_u32(const void* p) {
    uint32_t a;
    asm("{ .reg .u64 t; cvta.to.shared.u64 t, %1; cvt.u32.u64 %0, t; }" : "=r"(a) : "l"(p));
    return a;
}
#define CP_ASYNC16(dst, src) \
    asm volatile("cp.async.cg.shared.global [%0], [%1], 16;" :: "r"(dst), "l"(src) : "memory")
#define CP_COMMIT() asm volatile("cp.async.commit_group;" ::: "memory")

#define LDSM4(r, a) \
    asm volatile("ldmatrix.sync.aligned.m8n8.x4.shared.b16 {%0,%1,%2,%3}, [%4];" \
        : "=r"((r)[0]), "=r"((r)[1]), "=r"((r)[2]), "=r"((r)[3]) : "r"(a))

#define MMA16816(c, a, b0, b1) \
    asm volatile("mma.sync.aligned.m16n8k16.row.col.f32.f16.f16.f32 " \
        "{%0,%1,%2,%3}, {%4,%5,%6,%7}, {%8,%9}, {%0,%1,%2,%3};" \
        : "+f"((c)[0]), "+f"((c)[1]), "+f"((c)[2]), "+f"((c)[3]) \
        : "r"((a)[0]), "r"((a)[1]), "r"((a)[2]), "r"((a)[3]), "r"(b0), "r"(b1))

// ============================ cast kernels (fp32 -> fp16 hi) ============================
__global__ __launch_bounds__(256) void cast_desc(const float* __restrict__ src) {
    int i = blockIdx.x * 256 + threadIdx.x;           // float4 index
    if (i >= GM * GH / 4) return;
    float4 v = reinterpret_cast<const float4*>(src)[i];
    __half2* dst = reinterpret_cast<__half2*>(g_Ah);
    dst[2 * i]     = __floats2half2_rn(v.x, v.y);
    dst[2 * i + 1] = __floats2half2_rn(v.z, v.w);
}

__global__ __launch_bounds__(256) void cast_vocab(const float* __restrict__ vocab,
                                                  const float* __restrict__ defemb) {
    int i = blockIdx.x * 256 + threadIdx.x;           // float4 index over GN*GH/4
    if (i >= GN * GH / 4) return;
    int row = i >> 8;                                 // 256 float4 per row
    int col = i & 255;
    float4 v = (row < GD)
        ? reinterpret_cast<const float4*>(vocab)[(size_t)row * 256 + col]
        : reinterpret_cast<const float4*>(defemb)[col];
    __half2* dst = reinterpret_cast<__half2*>(g_Bh);
    dst[2 * i]     = __floats2half2_rn(v.x, v.y);
    dst[2 * i + 1] = __floats2half2_rn(v.z, v.w);
}

// ============================ HMMA GEMM (hh term, K=1024) ============================
__device__ __forceinline__ void load_stage(uint32_t smb, int buf, int s,
                                           int m0, int n0, int tid) {
    const int kk = s * KT;
    const uint32_t ao = smb + (uint32_t)buf * STG_BYTES;
    const uint32_t bo = ao + 16384u;
    const int r0 = tid >> 3, c8 = tid & 7;
    #pragma unroll
    for (int j = 0; j < 4; j++) {
        int row = r0 + j * 32;
        uint32_t x = (uint32_t)(c8 * 16) ^ (uint32_t)((row & 7) << 4);
        CP_ASYNC16(ao + (uint32_t)row * 128u + x,
                   g_Ah + (size_t)(m0 + row) * GH + kk + c8 * 8);
        CP_ASYNC16(bo + (uint32_t)row * 128u + x,
                   g_Bh + (size_t)(n0 + row) * GH + kk + c8 * 8);
    }
    CP_COMMIT();
}

__global__ __launch_bounds__(TPB, 2) void gemm_hmma(float* __restrict__ logits) {
    extern __shared__ char sm[];
    const uint32_t smb = smem_u32(sm);
    const int tid = threadIdx.x;
    const int wid = tid >> 5, lane = tid & 31;
    const int m0 = blockIdx.y * MT, n0 = blockIdx.x * NT;
    const int wm0 = (wid & 1) * 64, wn0 = (wid >> 1) * 32;

    float acc[4][4][4];
    #pragma unroll
    for (int i = 0; i < 4; i++)
        #pragma unroll
        for (int j = 0; j < 4; j++)
            #pragma unroll
            for (int k = 0; k < 4; k++) acc[i][j][k] = 0.0f;

    const int matid = lane >> 3, l7 = lane & 7;
    uint32_t a_base[4], a_xor[4];
    #pragma unroll
    for (int mi = 0; mi < 4; mi++) {
        int row = wm0 + mi * 16 + (matid & 1) * 8 + l7;
        a_base[mi] = (uint32_t)row * 128u;
        a_xor[mi] = (uint32_t)((row & 7) << 4);
    }
    const uint32_t a_colb = (uint32_t)((matid >> 1) * 16);
    const int brow = wn0 + matid * 8 + l7;
    const uint32_t b_base = 16384u + (uint32_t)brow * 128u;
    const uint32_t b_xor = (uint32_t)((brow & 7) << 4);

    load_stage(smb, 0, 0, m0, n0, tid);
    load_stage(smb, 1, 1, m0, n0, tid);

    for (int s = 0; s < NSTAGE; s++) {
        if (s >= NSTAGE - 2) asm volatile("cp.async.wait_group 0;" ::: "memory");
        else                 asm volatile("cp.async.wait_group 1;" ::: "memory");
        __syncthreads();
        if (s + 2 < NSTAGE) load_stage(smb, (s + 2) % 3, s + 2, m0, n0, tid);

        const uint32_t bufo = smb + (uint32_t)(s % 3) * STG_BYTES;
        #pragma unroll
        for (int k16 = 0; k16 < 4; k16++) {
            const uint32_t kk2 = (uint32_t)(k16 * 32);
            uint32_t a[4][4], b01[4], b23[4];
            #pragma unroll
            for (int mi = 0; mi < 4; mi++)
                LDSM4(a[mi], bufo + a_base[mi] + ((kk2 + a_colb) ^ a_xor[mi]));
            LDSM4(b01, bufo + b_base + (kk2 ^ b_xor));
            LDSM4(b23, bufo + b_base + ((kk2 + 16u) ^ b_xor));
            #pragma unroll
            for (int mi = 0; mi < 4; mi++)
                #pragma unroll
                for (int ni = 0; ni < 4; ni++)
                    MMA16816(acc[mi][ni], a[mi], b01[ni], b23[ni]);
        }
    }
    const int gid = lane >> 2, tig = lane & 3;
    #pragma unroll
    for (int mi = 0; mi < 4; mi++) {
        #pragma unroll
        for (int ni = 0; ni < 4; ni++) {
            const int n = n0 + wn0 + ni * 8 + tig * 2;
            const int mrow = m0 + wm0 + mi * 16 + gid;
            float* p0 = logits + (size_t)mrow * GN + n;
            float* p1 = p0 + 8 * (size_t)GN;
            if (n < GN)     { p0[0] = acc[mi][ni][0]; p1[0] = acc[mi][ni][2]; }
            if (n + 1 < GN) { p0[1] = acc[mi][ni][1]; p1[1] = acc[mi][ni][3]; }
        }
    }
}

// ============================ fused refine + softmax + blend ============================
// Per row: hh logits in sim. Find hh max, select candidates (> max-45),
// recompute their logits exactly in fp32, softmax whole row, sparse blend.
__global__ __launch_bounds__(256) void softmax_blend(
    const float* __restrict__ desc,
    const float* __restrict__ vocab,
    const float* __restrict__ defemb,
    float* __restrict__ sim,
    float* __restrict__ outc)
{
    __shared__ float srow[GN + 3];
    __shared__ float drow[GH];
    __shared__ float red[256];
    __shared__ unsigned short bidx[8 * WCAP];
    __shared__ unsigned short cidx[8 * WCAP];
    __shared__ int wcnt[8];

    const int m = blockIdx.x;
    const int tid = threadIdx.x;
    const int wid = tid >> 5, lane = tid & 31;
    float* simrow = sim + (size_t)m * GN;

    // desc row -> smem (float4)
    {
        const float4* s4 = reinterpret_cast<const float4*>(desc + (size_t)m * GH);
        reinterpret_cast<float4*>(drow)[tid] = s4[tid];
    }
    // load hh logits + row max
    float mx = -1e30f;
    for (int i = tid; i < GN; i += 256) {
        float v = simrow[i];
        srow[i] = v;
        mx = fmaxf(mx, v);
    }
    red[tid] = mx;
    __syncthreads();
    for (int s = 128; s > 0; s >>= 1) {
        if (tid < s) red[tid] = fmaxf(red[tid], red[tid + s]);
        __syncthreads();
    }
    const float mx0 = red[0];
    __syncthreads();

    // per-warp candidate scan (no block syncs inside)
    {
        const float thr = mx0 - CAND_SLACK;
        const int start = wid * 1251;
        const int end = min(start + 1251, GN);
        int c = 0;
        for (int base = start; base < end; base += 32) {
            int d = base + lane;
            bool sel = (d < end) && (srow[d] > thr);
            unsigned bal = __ballot_sync(0xffffffffu, sel);
            int pos = c + __popc(bal & ((1u << lane) - 1u));
            if (sel && pos < WCAP) bidx[wid * WCAP + pos] = (unsigned short)d;
            c += __popc(bal);
        }
        if (lane == 0) wcnt[wid] = min(c, WCAP);
    }
    __syncthreads();

    // flatten buckets -> cidx (deterministic order)
    int cnt = 0;
    {
        int offs[8];
        #pragma unroll
        for (int w = 0; w < 8; w++) { offs[w] = cnt; cnt += wcnt[w]; }
        for (int i = lane; i < wcnt[wid]; i += 32)
            cidx[offs[wid] + i] = bidx[wid * WCAP + i];
    }
    __syncthreads();

    // exact fp32 refinement: candidate g handled by warp (g % 8)
    for (int g = wid; g < cnt; g += 8) {
        const int d = cidx[g];
        const float4* v4 = (d < GD)
            ? reinterpret_cast<const float4*>(vocab + (size_t)d * GH)
            : reinterpret_cast<const float4*>(defemb);
        const float4* d4 = reinterpret_cast<const float4*>(drow);
        float s = 0.0f;
        #pragma unroll
        for (int e = 0; e < 8; e++) {
            float4 a = d4[lane + e * 32];
            float4 b = v4[lane + e * 32];
            s = fmaf(a.x, b.x, s); s = fmaf(a.y, b.y, s);
            s = fmaf(a.z, b.z, s); s = fmaf(a.w, b.w, s);
        }
        #pragma unroll
        for (int o = 16; o > 0; o >>= 1) s += __shfl_xor_sync(0xffffffffu, s, o);
        if (lane == 0) srow[d] = s;
    }
    __syncthreads();

    // refined max (true max is always a candidate)
    mx = -1e30f;
    for (int g = tid; g < cnt; g += 256) mx = fmaxf(mx, srow[cidx[g]]);
    red[tid] = mx;
    __syncthreads();
    for (int s = 128; s > 0; s >>= 1) {
        if (tid < s) red[tid] = fmaxf(red[tid], red[tid + s]);
        __syncthreads();
    }
    mx = red[0];
    __syncthreads();

    // exp + sum
    float sum = 0.0f;
    for (int i = tid; i < GN; i += 256) {
        float e = __expf(srow[i] - mx);
        srow[i] = e;
        sum += e;
    }
    red[tid] = sum;
    __syncthreads();
    for (int s = 128; s > 0; s >>= 1) {
        if (tid < s) red[tid] += red[tid + s];
        __syncthreads();
    }
    const float inv = 1.0f / red[0];
    __syncthreads();

    // normalize + write similarity
    for (int i = tid; i < GN; i += 256) {
        float v = srow[i] * inv;
        srow[i] = v;
        simrow[i] = v;
    }
    __syncthreads();

    // sparse blend over the candidate set
    float4 dv = reinterpret_cast<const float4*>(drow)[tid];
    const float sdef = srow[GD];
    float4 acc;
    acc.x = sdef * dv.x; acc.y = sdef * dv.y; acc.z = sdef * dv.z; acc.w = sdef * dv.w;

    const float4* v4 = reinterpret_cast<const float4*>(vocab);
    for (int g = 0; g < cnt; g++) {
        const int d = cidx[g];
        if (d < GD) {
            const float w = srow[d];
            if (w > SEL_EPS) {
                float4 v = v4[(size_t)d * (GH / 4) + tid];
                acc.x = fmaf(w, v.x, acc.x); acc.y = fmaf(w, v.y, acc.y);
                acc.z = fmaf(w, v.z, acc.z); acc.w = fmaf(w, v.w, acc.w);
            }
        }
    }
    reinterpret_cast<float4*>(outc)[(size_t)m * (GH / 4) + tid] = acc;
}

// ============================ launcher ============================
extern "C" void kernel_launch(void* const* d_in, const int* in_sizes, int n_in,
                              void* d_out, int out_size)
{
    const float* vocab = (const float*)d_in[0];   // (10000, 1024)
    const float* desc  = (const float*)d_in[1];   // (8, 512, 1024)
    const float* defe  = (const float*)d_in[2];   // (1024,)

    float* outc = (float*)d_out;
    float* sim  = outc + (size_t)GM * GH;

    cudaFuncSetAttribute(gemm_hmma, cudaFuncAttributeMaxDynamicSharedMemorySize, SMEM_ALLOC);

    cast_desc<<<GM * GH / 4 / 256, 256>>>(desc);
    cast_vocab<<<(GN * GH / 4 + 255) / 256, 256>>>(vocab, defe);

    dim3 g1((GN + NT - 1) / NT, GM / MT);   // (79, 32)
    gemm_hmma<<<g1, TPB, SMEM_ALLOC>>>(sim);
    softmax_blend<<<GM, 256>>>(desc, vocab, defe, sim, outc);
}